// round 2
// baseline (speedup 1.0000x reference)
#include <cuda_runtime.h>
#include <stdint.h>

// ---------------- problem constants / scratch sizing ----------------
#define N_MAX   131072      // >= 100000 columns
#define E_MAX   1700000     // >= 1600000 edges
#define EPSF    1e-8f
#define GAMMA   0.1
// LAMBDA = 1.0

// ---------------- device scratch (static, no allocation) ----------------
__device__ double             d_colsum[N_MAX];
__device__ int                d_count[N_MAX];
__device__ int                d_offsets[N_MAX + 1];
__device__ int                d_cursor[N_MAX];
__device__ unsigned long long d_edge[E_MAX];   // {row:32 | nv_bits:32}, binned by column
__device__ unsigned d_hist[2][256];            // dual radix-select histograms
__device__ unsigned d_selprefix[2];
__device__ unsigned d_selkmask;
__device__ unsigned d_selk[2];
__device__ float    d_selres[2];
__device__ double   d_part[3][256];            // sliced partials: 0=reg, 1=recon, 2=block
__device__ int      d_row64, d_col64;          // index dtype flags

// ---------------- helpers ----------------
__device__ __forceinline__ int getIdx(const void* p, int e, int is64) {
    return is64 ? (int)((const long long*)p)[e] : ((const int*)p)[e];
}

__device__ __forceinline__ double blockReduceD(double v) {
    __shared__ double ws[32];
    __syncthreads();
    int lane = threadIdx.x & 31, w = threadIdx.x >> 5;
    #pragma unroll
    for (int o = 16; o; o >>= 1) v += __shfl_xor_sync(0xFFFFFFFFu, v, o);
    if (!lane) ws[w] = v;
    __syncthreads();
    int nw = (blockDim.x + 31) >> 5;
    v = (threadIdx.x < nw) ? ws[threadIdx.x] : 0.0;
    if (w == 0) {
        #pragma unroll
        for (int o = 16; o; o >>= 1) v += __shfl_xor_sync(0xFFFFFFFFu, v, o);
    }
    return v;  // valid on thread 0
}

// ---------------- kernels ----------------
// zero scratch + detect index dtype (block 0): for int64 (<2^31), odd 32-bit
// words are all zero high halves.
__global__ void k_zero(const void* rowp, const void* colp, int n, int E) {
    int i = blockIdx.x * blockDim.x + threadIdx.x;
    if (i < n) { d_colsum[i] = 0.0; d_count[i] = 0; }
    if (i < 512) d_hist[i >> 8][i & 255] = 0u;
    if (i < 768) d_part[i >> 8][i & 255] = 0.0;
    if (i < 2) {
        d_selprefix[i] = 0u;
        d_selk[i]      = (unsigned)(E / 2 - 1 + i);  // two middle order stats
    }
    if (i == 0) d_selkmask = 0u;

    if (blockIdx.x == 0) {
        __shared__ int nzr, nzc;
        if (threadIdx.x == 0) { nzr = 0; nzc = 0; }
        __syncthreads();
        const unsigned* r = (const unsigned*)rowp;
        const unsigned* c = (const unsigned*)colp;
        for (int s = threadIdx.x; s < 512; s += blockDim.x) {
            int j = 2 * s + 1;  // odd words, index < E for either dtype
            if (r[j]) atomicOr(&nzr, 1);
            if (c[j]) atomicOr(&nzc, 1);
        }
        __syncthreads();
        if (threadIdx.x == 0) { d_row64 = nzr ? 0 : 1; d_col64 = nzc ? 0 : 1; }
    }
}

__global__ void k_count(const float* __restrict__ C, const void* __restrict__ colp, int E) {
    int e = blockIdx.x * blockDim.x + threadIdx.x;
    if (e >= E) return;
    int c = getIdx(colp, e, d_col64);
    atomicAdd(&d_count[c], 1);
    atomicAdd(&d_colsum[c], (double)C[e]);
}

// Single-block exclusive scan of counts -> offsets/cursor. Two-phase:
// per-thread chunk sums -> block scan -> per-thread serial writeback.
__global__ void k_scan(int n, int E) {
    __shared__ int s[1024];
    int t = threadIdx.x;                         // 1024 threads
    int per = (n + 1023) >> 10;
    int start = t * per;
    int end = min(start + per, n);
    int sum = 0;
    for (int i = start; i < end; i++) sum += d_count[i];
    s[t] = sum; __syncthreads();
    #pragma unroll
    for (int off = 1; off < 1024; off <<= 1) {
        int v = (t >= off) ? s[t - off] : 0;
        __syncthreads();
        s[t] += v;
        __syncthreads();
    }
    int run = s[t] - sum;                        // exclusive prefix
    for (int i = start; i < end; i++) {
        int c = d_count[i];
        d_offsets[i] = run;
        d_cursor[i]  = run;
        run += c;
    }
    if (t == 0) d_offsets[n] = E;
}

// norm_vals + regularization sum + scatter interleaved edge payloads into bins
__global__ void k_norm(const float* __restrict__ C, const void* __restrict__ rowp,
                       const void* __restrict__ colp, float* __restrict__ out, int E) {
    int e = blockIdx.x * blockDim.x + threadIdx.x;
    int r64 = d_row64, c64 = d_col64;
    float nv = 0.f;
    if (e < E) {
        int c = getIdx(colp, e, c64);
        int r = getIdx(rowp, e, r64);
        float cs = (float)d_colsum[c] + EPSF;
        nv = C[e] / cs;
        out[e] = nv;
        int pos = atomicAdd(&d_cursor[c], 1);
        d_edge[pos] = ((unsigned long long)(unsigned)r << 32) | (unsigned long long)__float_as_uint(nv);
    }
    double v = blockReduceD((double)nv * (double)nv);
    if (threadIdx.x == 0) atomicAdd(&d_part[0][blockIdx.x & 255], v);
}

// One warp per column: accumulate C^T Z row in registers (float4 per lane),
// fuse the (Z_recon - Z)^2 reduction. Z stays L2-resident after first touch.
__global__ void k_recon(const float4* __restrict__ Z4, int n) {
    int warp = (blockIdx.x * blockDim.x + threadIdx.x) >> 5;
    int lane = threadIdx.x & 31;
    float ssq = 0.f;
    if (warp < n) {
        int s = d_offsets[warp], e = d_offsets[warp + 1];
        float4 acc = make_float4(0.f, 0.f, 0.f, 0.f);
        int i = s;
        for (; i + 2 <= e; i += 2) {
            unsigned long long p0 = d_edge[i];
            unsigned long long p1 = d_edge[i + 1];
            float nv0 = __uint_as_float((unsigned)p0);
            float nv1 = __uint_as_float((unsigned)p1);
            const float4 z0 = __ldg(&Z4[(long)(unsigned)(p0 >> 32) * 32 + lane]);
            const float4 z1 = __ldg(&Z4[(long)(unsigned)(p1 >> 32) * 32 + lane]);
            acc.x = fmaf(nv0, z0.x, acc.x);
            acc.y = fmaf(nv0, z0.y, acc.y);
            acc.z = fmaf(nv0, z0.z, acc.z);
            acc.w = fmaf(nv0, z0.w, acc.w);
            acc.x = fmaf(nv1, z1.x, acc.x);
            acc.y = fmaf(nv1, z1.y, acc.y);
            acc.z = fmaf(nv1, z1.z, acc.z);
            acc.w = fmaf(nv1, z1.w, acc.w);
        }
        if (i < e) {
            unsigned long long p0 = d_edge[i];
            float nv0 = __uint_as_float((unsigned)p0);
            const float4 z0 = __ldg(&Z4[(long)(unsigned)(p0 >> 32) * 32 + lane]);
            acc.x = fmaf(nv0, z0.x, acc.x);
            acc.y = fmaf(nv0, z0.y, acc.y);
            acc.z = fmaf(nv0, z0.z, acc.z);
            acc.w = fmaf(nv0, z0.w, acc.w);
        }
        float4 zj = __ldg(&Z4[(long)warp * 32 + lane]);
        float dx = acc.x - zj.x, dy = acc.y - zj.y, dz = acc.z - zj.z, dw = acc.w - zj.w;
        ssq = dx * dx + dy * dy + dz * dz + dw * dw;
    }
    double v = blockReduceD((double)ssq);
    if (threadIdx.x == 0) atomicAdd(&d_part[1][blockIdx.x & 255], v);
}

// Dual radix-select histogram pass over |norm_vals| bit patterns: both target
// order statistics are advanced off the same read of the data.
__global__ void k_selhist(const float* __restrict__ out, int E, int shift) {
    __shared__ unsigned sh[2][256];
    for (int i = threadIdx.x; i < 512; i += blockDim.x) sh[i >> 8][i & 255] = 0u;
    __syncthreads();
    unsigned p0 = d_selprefix[0], p1 = d_selprefix[1], kmask = d_selkmask;
    for (int e = blockIdx.x * blockDim.x + threadIdx.x; e < E; e += gridDim.x * blockDim.x) {
        unsigned b = __float_as_uint(out[e]) & 0x7FFFFFFFu;
        unsigned m = b & kmask;
        unsigned byte = (b >> shift) & 0xFF;
        if (m == p0) atomicAdd(&sh[0][byte], 1u);
        if (m == p1) atomicAdd(&sh[1][byte], 1u);
    }
    __syncthreads();
    for (int i = threadIdx.x; i < 512; i += blockDim.x) {
        unsigned v = sh[i >> 8][i & 255];
        if (v) atomicAdd(&d_hist[i >> 8][i & 255], v);
    }
}

__global__ void k_selstep(int shift) {
    for (int w = 0; w < 2; w++) {
        unsigned cum = 0, k = d_selk[w];
        #pragma unroll 1
        for (int v = 0; v < 256; v++) {
            unsigned c = d_hist[w][v];
            if (k < cum + c) {
                d_selprefix[w] |= ((unsigned)v << shift);
                d_selk[w] = k - cum;
                break;
            }
            cum += c;
        }
        for (int v = 0; v < 256; v++) d_hist[w][v] = 0u;
        if (shift == 0) d_selres[w] = __uint_as_float(d_selprefix[w]);
    }
    d_selkmask |= (0xFFu << shift);
}

__global__ void k_block(const float* __restrict__ out, int E) {
    float thr = 0.5f * (d_selres[0] + d_selres[1]);
    double local = 0.0;
    for (int e = blockIdx.x * blockDim.x + threadIdx.x; e < E; e += gridDim.x * blockDim.x) {
        float nv = out[e];
        if (fabsf(nv) < thr) local += (double)nv * (double)nv;
    }
    double v = blockReduceD(local);
    if (threadIdx.x == 0) atomicAdd(&d_part[2][blockIdx.x & 255], v);
}

__global__ void k_fin(float* __restrict__ out, int base, int n) {
    int t = threadIdx.x;  // 256 threads
    double reg = blockReduceD(d_part[0][t]);
    double rec = blockReduceD(d_part[1][t]);
    double blk = blockReduceD(d_part[2][t]);
    if (t == 0) {
        out[base + 0] = (float)(rec / ((double)n * 128.0));  // recon_loss (mean)
        out[base + 1] = (float)reg;                          // reg_loss (LAMBDA=1)
        out[base + 2] = (float)(GAMMA * blk);                // block_loss
    }
}

// ---------------- launch ----------------
extern "C" void kernel_launch(void* const* d_in, const int* in_sizes, int n_in,
                              void* d_out, int out_size) {
    const float* Z    = (const float*)d_in[0];
    const float* C    = (const float*)d_in[1];
    const void*  rowp = d_in[2];
    const void*  colp = d_in[3];
    float* out = (float*)d_out;

    int n = in_sizes[0] / 128;   // N_SAMPLES
    int E = in_sizes[1];         // NUM_EDGES

    const int TB = 256;
    int gE = (E + TB - 1) / TB;
    int gN = (n + TB - 1) / TB;

    k_zero<<<gN, TB>>>(rowp, colp, n, E);
    k_count<<<gE, TB>>>(C, colp, E);
    k_scan<<<1, 1024>>>(n, E);
    k_norm<<<gE, TB>>>(C, rowp, colp, out, E);
    k_recon<<<(n * 32 + 255) / 256, 256>>>((const float4*)Z, n);
    for (int p = 0; p < 4; p++) {
        k_selhist<<<512, 256>>>(out, E, 24 - 8 * p);
        k_selstep<<<1, 1>>>(24 - 8 * p);
    }
    k_block<<<512, 256>>>(out, E);
    k_fin<<<1, 256>>>(out, out_size - 3, n);
}